// round 1
// baseline (speedup 1.0000x reference)
#include <cuda_runtime.h>
#include <math.h>

// Problem constants
#define B_DIM 64
#define S_DIM 4096
#define D_DIM 256
#define LN_EPS 1e-3f

// Kernel A tiling: 8 warps/CTA, 16 rows/warp -> 128 rows per CTA
#define WPB 8
#define RPW 16
#define ROWS_PER_CTA (WPB * RPW)           // 128
#define CTAS_PER_B (S_DIM / ROWS_PER_CTA)  // 32
#define PARTIALS_PER_B (CTAS_PER_B * WPB)  // 256

// Scratch: per-(batch, warp-partial) online-softmax state.
// acc: [B][PARTIALS][D] so kernel B reads coalesced across d.
__device__ float g_acc[B_DIM * PARTIALS_PER_B * D_DIM];  // 16 MB
__device__ float g_m[B_DIM * PARTIALS_PER_B];
__device__ float g_l[B_DIM * PARTIALS_PER_B];

__device__ __forceinline__ float warp_sum(float v) {
#pragma unroll
    for (int off = 16; off > 0; off >>= 1)
        v += __shfl_xor_sync(0xffffffffu, v, off);
    return v;
}

// ---------------------------------------------------------------------------
// Kernel A: single pass over x. Each warp processes 16 consecutive rows of one
// batch: computes LN+Dense score algebraically from (sum x, sum x^2, dot(x,gw))
// while the row sits in registers, then does the online-softmax weighted
// accumulation in registers. Writes one (m, l, acc[256]) partial per warp.
// ---------------------------------------------------------------------------
__global__ __launch_bounds__(WPB * 32) void attn_pool_pass1(
    const float* __restrict__ x, const float* __restrict__ mask,
    const float* __restrict__ gamma, const float* __restrict__ beta,
    const float* __restrict__ w, const float* __restrict__ bias_p) {
    const int b = blockIdx.y;
    const int warp = threadIdx.x >> 5;
    const int lane = threadIdx.x & 31;
    const int d0 = lane * 8;

    // Per-lane gamma*w and the reduced constants GW, BW (uniform per warp).
    float gw[8];
    float gwsum = 0.f, bwsum = 0.f;
#pragma unroll
    for (int i = 0; i < 8; i++) {
        float wi = w[d0 + i];
        gw[i] = gamma[d0 + i] * wi;
        gwsum += gw[i];
        bwsum += beta[d0 + i] * wi;
    }
    const float GW = warp_sum(gwsum);
    const float BW = warp_sum(bwsum) + bias_p[0];

    const int row0 = blockIdx.x * ROWS_PER_CTA + warp * RPW;
    const float* xb = x + ((size_t)b * S_DIM + row0) * D_DIM;
    const float* mb = mask + (size_t)b * S_DIM + row0;

    float m = -INFINITY;
    float l = 0.f;
    float acc[8];
#pragma unroll
    for (int i = 0; i < 8; i++) acc[i] = 0.f;

    for (int r = 0; r < RPW; r++) {
        // Load one row: 2 independent float4 per lane, coalesced 1KB/warp.
        const float4 v0 = *reinterpret_cast<const float4*>(xb + (size_t)r * D_DIM + d0);
        const float4 v1 = *reinterpret_cast<const float4*>(xb + (size_t)r * D_DIM + d0 + 4);
        float xv[8] = {v0.x, v0.y, v0.z, v0.w, v1.x, v1.y, v1.z, v1.w};

        float sx = 0.f, sxx = 0.f, sdot = 0.f;
#pragma unroll
        for (int i = 0; i < 8; i++) {
            sx += xv[i];
            sxx = fmaf(xv[i], xv[i], sxx);
            sdot = fmaf(xv[i], gw[i], sdot);
        }
        // Three warp reductions, interleaved to overlap shfl latency.
#pragma unroll
        for (int off = 16; off > 0; off >>= 1) {
            sx += __shfl_xor_sync(0xffffffffu, sx, off);
            sxx += __shfl_xor_sync(0xffffffffu, sxx, off);
            sdot += __shfl_xor_sync(0xffffffffu, sdot, off);
        }

        const float mu = sx * (1.f / D_DIM);
        const float var = sxx * (1.f / D_DIM) - mu * mu;
        const float rstd = rsqrtf(var + LN_EPS);
        float score = rstd * (sdot - mu * GW) + BW;
        const float mk = mb[r];
        score += (1.f - mk) * -1e9f;

        // Online softmax update (warp-uniform score).
        const float mnew = fmaxf(m, score);
        const float c = __expf(m - mnew);    // first iter: exp(-inf)=0
        const float p = __expf(score - mnew);
        l = l * c + p;
#pragma unroll
        for (int i = 0; i < 8; i++) acc[i] = fmaf(acc[i], c, p * xv[i]);
        m = mnew;
    }

    // Write partial
    const int ip = blockIdx.x * WPB + warp;  // 0..255 within batch
    const size_t pbase = ((size_t)b * PARTIALS_PER_B + ip);
    if (lane == 0) {
        g_m[pbase] = m;
        g_l[pbase] = l;
    }
    float* ab = g_acc + pbase * D_DIM + d0;
#pragma unroll
    for (int i = 0; i < 8; i++) ab[i] = acc[i];
}

// ---------------------------------------------------------------------------
// Kernel B: combine 256 partials per batch. 64 CTAs x 256 threads.
// Thread d owns output dim d; reads of g_acc are coalesced across threads.
// ---------------------------------------------------------------------------
__global__ __launch_bounds__(256) void attn_pool_pass2(float* __restrict__ out) {
    const int b = blockIdx.x;
    const int t = threadIdx.x;  // 0..255: doubles as partial index and d index
    const int warp = t >> 5, lane = t & 31;

    __shared__ float red[8];
    __shared__ float Msh, Lsh;
    __shared__ float sscale[PARTIALS_PER_B];

    const size_t pb = (size_t)b * PARTIALS_PER_B;
    const float md = g_m[pb + t];

    // Block max of m
    float v = md;
#pragma unroll
    for (int off = 16; off > 0; off >>= 1)
        v = fmaxf(v, __shfl_xor_sync(0xffffffffu, v, off));
    if (lane == 0) red[warp] = v;
    __syncthreads();
    if (t == 0) {
        float mm = red[0];
#pragma unroll
        for (int i = 1; i < 8; i++) mm = fmaxf(mm, red[i]);
        Msh = mm;
    }
    __syncthreads();
    const float M = Msh;

    const float sc = __expf(md - M);
    sscale[t] = sc;

    // Block sum of l * scale
    float ls = g_l[pb + t] * sc;
#pragma unroll
    for (int off = 16; off > 0; off >>= 1)
        ls += __shfl_xor_sync(0xffffffffu, ls, off);
    if (lane == 0) red[warp] = ls;
    __syncthreads();
    if (t == 0) {
        float s = 0.f;
#pragma unroll
        for (int i = 0; i < 8; i++) s += red[i];
        Lsh = s;
    }
    __syncthreads();
    const float Linv = 1.f / Lsh;

    // out[b][d] = sum_i acc[i][d] * scale[i] / L
    const float* ab = g_acc + pb * D_DIM + t;
    float o = 0.f;
#pragma unroll 8
    for (int i = 0; i < PARTIALS_PER_B; i++) {
        o = fmaf(ab[(size_t)i * D_DIM], sscale[i], o);
    }
    out[(size_t)b * D_DIM + t] = o * Linv;
}

extern "C" void kernel_launch(void* const* d_in, const int* in_sizes, int n_in,
                              void* d_out, int out_size) {
    const float* x = (const float*)d_in[0];      // [64,4096,256]
    const float* mask = (const float*)d_in[1];   // [64,4096]
    const float* gamma = (const float*)d_in[2];  // [256]
    const float* beta = (const float*)d_in[3];   // [256]
    const float* w = (const float*)d_in[4];      // [256]
    const float* bias = (const float*)d_in[5];   // scalar
    float* out = (float*)d_out;                  // [64,256]

    dim3 grid1(CTAS_PER_B, B_DIM);
    attn_pool_pass1<<<grid1, WPB * 32>>>(x, mask, gamma, beta, w, bias);
    attn_pool_pass2<<<B_DIM, 256>>>(out);
}

// round 2
// speedup vs baseline: 1.3567x; 1.3567x over previous
#include <cuda_runtime.h>
#include <math.h>

// Problem constants
#define B_DIM 64
#define S_DIM 4096
#define D_DIM 256
#define LN_EPS 1e-3f

// Pass1 tiling: 8 warps/CTA, 32 rows/warp -> 256 rows per CTA
#define WPB 8
#define RPW 32
#define ROWS_PER_CTA (WPB * RPW)           // 256
#define CTAS_PER_B (S_DIM / ROWS_PER_CTA)  // 16
#define PARTIALS_PER_B (CTAS_PER_B * WPB)  // 128

// Pass2 split: 8 CTAs per batch, 16 partials each
#define SPLIT2 8
#define CHUNK2 (PARTIALS_PER_B / SPLIT2)   // 16

// Scratch
__device__ float g_acc[B_DIM * PARTIALS_PER_B * D_DIM];   // 8 MB
__device__ float g_m[B_DIM * PARTIALS_PER_B];
__device__ float g_l[B_DIM * PARTIALS_PER_B];
__device__ float g_part[SPLIT2 * B_DIM * D_DIM];          // 512 KB

__device__ __forceinline__ float warp_sum(float v) {
#pragma unroll
    for (int off = 16; off > 0; off >>= 1)
        v += __shfl_xor_sync(0xffffffffu, v, off);
    return v;
}

// ---------------------------------------------------------------------------
// Pass 1: single pass over x. Each warp: 32 consecutive rows, 2 rows per
// iteration (interleaved reduce chains + one combined online-softmax rescale).
// ---------------------------------------------------------------------------
__global__ __launch_bounds__(WPB * 32) void attn_pool_pass1(
    const float* __restrict__ x, const float* __restrict__ mask,
    const float* __restrict__ gamma, const float* __restrict__ beta,
    const float* __restrict__ w, const float* __restrict__ bias_p) {
    const int b = blockIdx.y;
    const int warp = threadIdx.x >> 5;
    const int lane = threadIdx.x & 31;
    const int d0 = lane * 8;

    // Per-lane gamma*w; warp-uniform constants GW, BW.
    float gw[8];
    float gwsum = 0.f, bwsum = 0.f;
#pragma unroll
    for (int i = 0; i < 8; i++) {
        float wi = w[d0 + i];
        gw[i] = gamma[d0 + i] * wi;
        gwsum += gw[i];
        bwsum += beta[d0 + i] * wi;
    }
    const float GW = warp_sum(gwsum);
    const float BW = warp_sum(bwsum) + bias_p[0];

    const int row0 = blockIdx.x * ROWS_PER_CTA + warp * RPW;
    const float* xb = x + ((size_t)b * S_DIM + row0) * D_DIM;
    const float* mb = mask + (size_t)b * S_DIM + row0;

    float m = -INFINITY;
    float l = 0.f;
    float acc[8];
#pragma unroll
    for (int i = 0; i < 8; i++) acc[i] = 0.f;

    for (int r = 0; r < RPW; r += 2) {
        // Two rows: 4 independent LDG.128 per lane, coalesced.
        const float* rp = xb + (size_t)r * D_DIM + d0;
        const float4 a0 = *reinterpret_cast<const float4*>(rp);
        const float4 a1 = *reinterpret_cast<const float4*>(rp + 4);
        const float4 b0 = *reinterpret_cast<const float4*>(rp + D_DIM);
        const float4 b1 = *reinterpret_cast<const float4*>(rp + D_DIM + 4);
        const float2 mk = *reinterpret_cast<const float2*>(mb + r);
        float xa[8] = {a0.x, a0.y, a0.z, a0.w, a1.x, a1.y, a1.z, a1.w};
        float xc[8] = {b0.x, b0.y, b0.z, b0.w, b1.x, b1.y, b1.z, b1.w};

        float sxA = 0.f, sxxA = 0.f, sdA = 0.f;
        float sxB = 0.f, sxxB = 0.f, sdB = 0.f;
#pragma unroll
        for (int i = 0; i < 8; i++) {
            sxA += xa[i];
            sxxA = fmaf(xa[i], xa[i], sxxA);
            sdA = fmaf(xa[i], gw[i], sdA);
            sxB += xc[i];
            sxxB = fmaf(xc[i], xc[i], sxxB);
            sdB = fmaf(xc[i], gw[i], sdB);
        }
        // Six interleaved warp reductions (independent chains).
#pragma unroll
        for (int off = 16; off > 0; off >>= 1) {
            sxA += __shfl_xor_sync(0xffffffffu, sxA, off);
            sxB += __shfl_xor_sync(0xffffffffu, sxB, off);
            sxxA += __shfl_xor_sync(0xffffffffu, sxxA, off);
            sxxB += __shfl_xor_sync(0xffffffffu, sxxB, off);
            sdA += __shfl_xor_sync(0xffffffffu, sdA, off);
            sdB += __shfl_xor_sync(0xffffffffu, sdB, off);
        }

        const float muA = sxA * (1.f / D_DIM);
        const float muB = sxB * (1.f / D_DIM);
        const float varA = sxxA * (1.f / D_DIM) - muA * muA;
        const float varB = sxxB * (1.f / D_DIM) - muB * muB;
        const float rsA = rsqrtf(varA + LN_EPS);
        const float rsB = rsqrtf(varB + LN_EPS);
        float sA = rsA * (sdA - muA * GW) + BW + (1.f - mk.x) * -1e9f;
        float sB = rsB * (sdB - muB * GW) + BW + (1.f - mk.y) * -1e9f;

        // Combined online-softmax update for both rows (one rescale).
        const float mnew = fmaxf(m, fmaxf(sA, sB));
        const float c = __expf(m - mnew);   // first iter: exp(-inf)=0
        const float pA = __expf(sA - mnew);
        const float pB = __expf(sB - mnew);
        l = fmaf(l, c, pA + pB);
#pragma unroll
        for (int i = 0; i < 8; i++)
            acc[i] = fmaf(acc[i], c, fmaf(pA, xa[i], pB * xc[i]));
        m = mnew;
    }

    // Write partial state.
    const int ip = blockIdx.x * WPB + warp;  // 0..127 within batch
    const size_t pbase = (size_t)b * PARTIALS_PER_B + ip;
    if (lane == 0) {
        g_m[pbase] = m;
        g_l[pbase] = l;
    }
    float* ab = g_acc + pbase * D_DIM + d0;
    *reinterpret_cast<float4*>(ab) = make_float4(acc[0], acc[1], acc[2], acc[3]);
    *reinterpret_cast<float4*>(ab + 4) = make_float4(acc[4], acc[5], acc[6], acc[7]);
}

// ---------------------------------------------------------------------------
// Pass 2: grid (B, SPLIT2). Each CTA redundantly computes M and L from the
// 128 (m,l) pairs, then reduces its 16-partial chunk over all 256 dims.
// ---------------------------------------------------------------------------
__global__ __launch_bounds__(256) void attn_pool_pass2() {
    const int b = blockIdx.x;
    const int split = blockIdx.y;
    const int t = threadIdx.x;
    const int warp = t >> 5, lane = t & 31;

    __shared__ float red[8];
    __shared__ float Msh, Lsh;
    __shared__ float scoef[CHUNK2];

    const size_t pb = (size_t)b * PARTIALS_PER_B;

    // Block max over 128 m values (threads 0..127 participate).
    float mv = (t < PARTIALS_PER_B) ? g_m[pb + t] : -INFINITY;
    float v = mv;
#pragma unroll
    for (int off = 16; off > 0; off >>= 1)
        v = fmaxf(v, __shfl_xor_sync(0xffffffffu, v, off));
    if (lane == 0) red[warp] = v;
    __syncthreads();
    if (t == 0) {
        float mm = red[0];
#pragma unroll
        for (int i = 1; i < 8; i++) mm = fmaxf(mm, red[i]);
        Msh = mm;
    }
    __syncthreads();
    const float M = Msh;

    // Block sum of l * exp(m - M).
    const float sc = (t < PARTIALS_PER_B) ? __expf(mv - M) : 0.f;
    float ls = (t < PARTIALS_PER_B) ? g_l[pb + t] * sc : 0.f;
#pragma unroll
    for (int off = 16; off > 0; off >>= 1)
        ls += __shfl_xor_sync(0xffffffffu, ls, off);
    if (lane == 0) red[warp] = ls;
    __syncthreads();
    if (t == 0) {
        float s = 0.f;
#pragma unroll
        for (int i = 0; i < 8; i++) s += red[i];
        Lsh = s;
    }
    __syncthreads();
    const float Linv = 1.f / Lsh;

    // Coefficients for this CTA's chunk.
    const int i0 = split * CHUNK2;
    if (t < CHUNK2) {
        scoef[t] = __expf(g_m[pb + i0 + t] - M) * Linv;
    }
    __syncthreads();

    // Sum chunk over dim t (coalesced across threads, 16 independent loads).
    const float* ab = g_acc + (pb + i0) * D_DIM + t;
    float o = 0.f;
#pragma unroll
    for (int i = 0; i < CHUNK2; i++)
        o = fmaf(ab[(size_t)i * D_DIM], scoef[i], o);
    g_part[((size_t)split * B_DIM + b) * D_DIM + t] = o;
}

// ---------------------------------------------------------------------------
// Pass 3: sum the SPLIT2 partial outputs. 64 CTAs x 256 threads.
// ---------------------------------------------------------------------------
__global__ __launch_bounds__(256) void attn_pool_pass3(float* __restrict__ out) {
    const int b = blockIdx.x;
    const int t = threadIdx.x;
    float o = 0.f;
#pragma unroll
    for (int s = 0; s < SPLIT2; s++)
        o += g_part[((size_t)s * B_DIM + b) * D_DIM + t];
    out[(size_t)b * D_DIM + t] = o;
}

extern "C" void kernel_launch(void* const* d_in, const int* in_sizes, int n_in,
                              void* d_out, int out_size) {
    const float* x = (const float*)d_in[0];      // [64,4096,256]
    const float* mask = (const float*)d_in[1];   // [64,4096]
    const float* gamma = (const float*)d_in[2];  // [256]
    const float* beta = (const float*)d_in[3];   // [256]
    const float* w = (const float*)d_in[4];      // [256]
    const float* bias = (const float*)d_in[5];   // scalar
    float* out = (float*)d_out;                  // [64,256]

    dim3 grid1(CTAS_PER_B, B_DIM);
    attn_pool_pass1<<<grid1, WPB * 32>>>(x, mask, gamma, beta, w, bias);
    dim3 grid2(B_DIM, SPLIT2);
    attn_pool_pass2<<<grid2, 256>>>();
    attn_pool_pass3<<<B_DIM, 256>>>(out);
}